// round 9
// baseline (speedup 1.0000x reference)
#include <cuda_runtime.h>
#include <cuda_bf16.h>
#include <cuda_fp16.h>
#include <cstdint>

// Problem constants (fixed by the dataset)
#define NE 50000
#define NR 2000
#define EMAX 800000
#define NHEAD 8
#define DIM 128
#define NEG_SLOPE 0.01f
#define NSEG (2 * NE)
#define TILE 512
#define NTILES ((NSEG + TILE - 1) / TILE)   // 196

// ---------------- scratch (static device globals; no allocation) -------------
__device__ float g_ph[NE * NHEAD];      // x_e @ Wh.T
__device__ float g_pt[NE * NHEAD];      // x_e @ Wt.T
__device__ float g_pr[NR * NHEAD];      // x_r @ Wr.T
__device__ uint4 g_xrh4[NR * DIM / 8];  // x_r in fp16, 16 uint4 (256B) per row
__device__ int   g_deg[NSEG];           // degrees: [0,NE)=h side, [NE,2NE)=t side
__device__ int   g_coffs[NSEG + 1];     // exclusive offsets (combined h|t CSR)
__device__ int   g_cur[NSEG];           // scatter cursors
__device__ int   g_elist[2 * EMAX];     // rel id per slot, grouped by (side,node)
__device__ int2  g_ht[EMAX];            // decoded (h, t) per edge
__device__ int   g_rel32[EMAX];         // rel cast to int32
__device__ int   g_tsum[NTILES];        // per-tile degree sums
__device__ int   g_toff[NTILES];        // per-tile exclusive offsets
__device__ int   g_is64;                // 1 if edge_index/rel are int64

__device__ __forceinline__ float lrelu(float s) {
    return (s > 0.0f) ? s : NEG_SLOPE * s;
}

// ---------------- kernel 0: zero degrees + detect index width ----------------
__global__ void k_zero_detect(const unsigned* ei_words) {
    int i = blockIdx.x * blockDim.x + threadIdx.x;
    if (i < NSEG) g_deg[i] = 0;
    if (blockIdx.x == 0 && threadIdx.x < 32) {
        unsigned w = ei_words[2 * threadIdx.x + 1];
        unsigned ball = __ballot_sync(0xffffffffu, w == 0u);
        if (threadIdx.x == 0) g_is64 = (ball == 0xffffffffu) ? 1 : 0;
    }
}

// ---------------- kernel 0b: convert x_r to fp16 ------------------------------
__global__ void k_cvt(const float* __restrict__ x_r) {
    int i = blockIdx.x * blockDim.x + threadIdx.x;
    if (i >= NR * DIM / 4) return;
    float4 v = ((const float4*)x_r)[i];
    __half2* dst = (__half2*)g_xrh4;
    dst[i * 2]     = __floats2half2_rn(v.x, v.y);
    dst[i * 2 + 1] = __floats2half2_rn(v.z, v.w);
}

// ---------------- kernel 1: projections (warp per row) -----------------------
__global__ __launch_bounds__(256) void k_proj(const float* __restrict__ x,
                                              const float* __restrict__ Wa,
                                              const float* __restrict__ Wb,
                                              int n, int mode) {
    int w = (blockIdx.x * blockDim.x + threadIdx.x) >> 5;
    int lane = threadIdx.x & 31;
    if (w >= n) return;
    float* pa = (mode == 0) ? g_ph : g_pr;
    float* pb = (mode == 0) ? g_pt : nullptr;

    const float* xr = x + (long)w * DIM;
    float x0 = xr[lane], x1 = xr[lane + 32], x2 = xr[lane + 64], x3 = xr[lane + 96];

#pragma unroll
    for (int h = 0; h < NHEAD; h++) {
        const float* wa = Wa + h * DIM;
        float a = x0 * wa[lane] + x1 * wa[lane + 32] + x2 * wa[lane + 64] + x3 * wa[lane + 96];
#pragma unroll
        for (int off = 16; off > 0; off >>= 1) a += __shfl_xor_sync(0xffffffffu, a, off);
        if (lane == 0) pa[w * NHEAD + h] = a;
        if (pb) {
            const float* wb = Wb + h * DIM;
            float b = x0 * wb[lane] + x1 * wb[lane + 32] + x2 * wb[lane + 64] + x3 * wb[lane + 96];
#pragma unroll
            for (int off = 16; off > 0; off >>= 1) b += __shfl_xor_sync(0xffffffffu, b, off);
            if (lane == 0) pb[w * NHEAD + h] = b;
        }
    }
}

// ---------------- kernel 2: decode + degree histogram (1 edge/thread) --------
__global__ __launch_bounds__(256) void k_hist(const void* __restrict__ ei,
                                              const void* __restrict__ rel, int E) {
    int e = blockIdx.x * blockDim.x + threadIdx.x;
    if (e >= E) return;
    int is64 = g_is64;
    int h, t, r;
    if (is64) {
        h = (int)((const long long*)ei)[e];
        t = (int)((const long long*)ei)[(long)E + e];
        r = (int)((const long long*)rel)[e];
    } else {
        h = ((const int*)ei)[e];
        t = ((const int*)ei)[(long)E + e];
        r = ((const int*)rel)[e];
    }
    g_ht[e] = make_int2(h, t);
    g_rel32[e] = r;
    atomicAdd(&g_deg[h], 1);
    atomicAdd(&g_deg[NE + t], 1);
}

// ---------------- kernels 3a/3b/3c: parallel exclusive scan ------------------
__global__ __launch_bounds__(256) void k_scan_a() {
    __shared__ int sh[256];
    int tid = threadIdx.x;
    int i0 = blockIdx.x * TILE + tid * 2;
    int v = 0;
    if (i0 < NSEG) v += g_deg[i0];
    if (i0 + 1 < NSEG) v += g_deg[i0 + 1];
    sh[tid] = v;
    __syncthreads();
    for (int off = 128; off > 0; off >>= 1) {
        if (tid < off) sh[tid] += sh[tid + off];
        __syncthreads();
    }
    if (tid == 0) g_tsum[blockIdx.x] = sh[0];
}

__global__ __launch_bounds__(256) void k_scan_b(int E) {
    __shared__ int sh[256];
    int tid = threadIdx.x;
    int v = (tid < NTILES) ? g_tsum[tid] : 0;
    sh[tid] = v;
    __syncthreads();
    for (int off = 1; off < 256; off <<= 1) {
        int t = 0;
        if (tid >= off) t = sh[tid - off];
        __syncthreads();
        sh[tid] += t;
        __syncthreads();
    }
    if (tid < NTILES) g_toff[tid] = sh[tid] - v;   // exclusive
    if (tid == 0) g_coffs[NSEG] = 2 * E;
}

__global__ __launch_bounds__(512) void k_scan_c() {
    __shared__ int sh[512];
    int tid = threadIdx.x;
    int idx = blockIdx.x * TILE + tid;
    int v = (idx < NSEG) ? g_deg[idx] : 0;
    sh[tid] = v;
    __syncthreads();
    for (int off = 1; off < 512; off <<= 1) {
        int t = 0;
        if (tid >= off) t = sh[tid - off];
        __syncthreads();
        sh[tid] += t;
        __syncthreads();
    }
    if (idx < NSEG) {
        int excl = g_toff[blockIdx.x] + sh[tid] - v;
        g_coffs[idx] = excl;
        g_cur[idx] = excl;
    }
}

// ---------------- kernel 4: counting-sort scatter (1 edge/thread) ------------
__global__ __launch_bounds__(256) void k_fill(int E) {
    int e = blockIdx.x * blockDim.x + threadIdx.x;
    if (e >= E) return;
    int2 ht = g_ht[e];
    int r = g_rel32[e];
    int p1 = atomicAdd(&g_cur[ht.x], 1);
    g_elist[p1] = r;
    int p2 = atomicAdd(&g_cur[NE + ht.y], 1);
    g_elist[p2] = r;
}

// ---------------- kernel 5: softmax + aggregation (fp16 x_r gather) ----------
// One warp per (side, node). Phase 1 keeps each lane's rel id (first 32 edges)
// in ONE register; phase 2 gets r via shuffle (26cyc) instead of re-loading
// g_elist (~234cyc L2), so the fp16 gathers issue immediately.
__global__ __launch_bounds__(256) void k_agg(float* __restrict__ out) {
    __shared__ __align__(16) float s_out[8][128];
    int wslot = threadIdx.x >> 5;
    int gw = (blockIdx.x * blockDim.x + threadIdx.x) >> 5;
    int lane = threadIdx.x & 31;
    if (gw >= NSEG) return;
    int side = (gw >= NE) ? 1 : 0;
    int node = side ? (gw - NE) : gw;
    const float* p = side ? g_pt : g_ph;

    int start = g_coffs[gw];
    int end = g_coffs[gw + 1];

    const float4* pn4 = (const float4*)(p + node * NHEAD);
    float4 pnA = pn4[0], pnB = pn4[1];
    float pn[NHEAD] = {pnA.x, pnA.y, pnA.z, pnA.w, pnB.x, pnB.y, pnB.z, pnB.w};

    // ---- phase 1: denominators per head; cache this lane's rel id -----------
    float exs[NHEAD];
#pragma unroll
    for (int h = 0; h < NHEAD; h++) exs[h] = 0.0f;
    int r_lane = 0;
    for (int j = start + lane; j < end; j += 32) {
        int r = g_elist[j];
        if (j == start + lane) r_lane = r;       // first pass: keep in register
        const float4* pr4 = (const float4*)(g_pr + r * NHEAD);
        float4 A = pr4[0], B = pr4[1];
        exs[0] += __expf(lrelu(pn[0] + A.x));
        exs[1] += __expf(lrelu(pn[1] + A.y));
        exs[2] += __expf(lrelu(pn[2] + A.z));
        exs[3] += __expf(lrelu(pn[3] + A.w));
        exs[4] += __expf(lrelu(pn[4] + B.x));
        exs[5] += __expf(lrelu(pn[5] + B.y));
        exs[6] += __expf(lrelu(pn[6] + B.z));
        exs[7] += __expf(lrelu(pn[7] + B.w));
    }
#pragma unroll
    for (int h = 0; h < NHEAD; h++) {
        float v = exs[h];
#pragma unroll
        for (int off = 16; off > 0; off >>= 1) v += __shfl_xor_sync(0xffffffffu, v, off);
        exs[h] = v;
    }

    int myh = lane & 7;
    int myg = lane >> 3;
    float pn_my = 0.0f, den_my = 0.0f;
#pragma unroll
    for (int h = 0; h < NHEAD; h++) {
        pn_my = (myh == h) ? pn[h] : pn_my;
        den_my = (myh == h) ? exs[h] : den_my;
    }
    float invd_my = 1.0f / (den_my + 1e-16f);

    int cend = (end < start + 32) ? end : (start + 32);

    // ---- phase 2: 4 edges/iter via 8-lane groups; r via shuffle -------------
    float accA[8], accB[8];
#pragma unroll
    for (int i = 0; i < 8; i++) { accA[i] = 0.0f; accB[i] = 0.0f; }

#define PROC4(BASE)                                                            \
    {                                                                          \
        int r = __shfl_sync(0xffffffffu, r_lane, (BASE) - start + myg);        \
        float ex = __expf(lrelu(pn_my + g_pr[r * NHEAD + myh])) * invd_my;     \
        ex += __shfl_xor_sync(0xffffffffu, ex, 1);                             \
        ex += __shfl_xor_sync(0xffffffffu, ex, 2);                             \
        ex += __shfl_xor_sync(0xffffffffu, ex, 4);                             \
        float a = ex * 0.125f;                                                 \
        const uint4* row = g_xrh4 + r * 16;                                    \
        uint4 u0 = row[myh];                                                   \
        uint4 u1 = row[myh + 8];                                               \
        float2 q;                                                              \
        q = __half22float2(*(__half2*)&u0.x); accA[0] += a * q.x; accA[1] += a * q.y; \
        q = __half22float2(*(__half2*)&u0.y); accA[2] += a * q.x; accA[3] += a * q.y; \
        q = __half22float2(*(__half2*)&u0.z); accA[4] += a * q.x; accA[5] += a * q.y; \
        q = __half22float2(*(__half2*)&u0.w); accA[6] += a * q.x; accA[7] += a * q.y; \
        q = __half22float2(*(__half2*)&u1.x); accB[0] += a * q.x; accB[1] += a * q.y; \
        q = __half22float2(*(__half2*)&u1.y); accB[2] += a * q.x; accB[3] += a * q.y; \
        q = __half22float2(*(__half2*)&u1.z); accB[4] += a * q.x; accB[5] += a * q.y; \
        q = __half22float2(*(__half2*)&u1.w); accB[6] += a * q.x; accB[7] += a * q.y; \
    }

    int jb = start;
    for (; jb + 8 <= cend; jb += 8) {
        PROC4(jb)
        PROC4(jb + 4)
    }
    if (jb + 4 <= cend) {
        PROC4(jb)
        jb += 4;
    }
#undef PROC4

    // reduce accumulators across the 4 groups (xor 8, 16)
#pragma unroll
    for (int i = 0; i < 8; i++) {
        accA[i] += __shfl_xor_sync(0xffffffffu, accA[i], 8);
        accA[i] += __shfl_xor_sync(0xffffffffu, accA[i], 16);
        accB[i] += __shfl_xor_sync(0xffffffffu, accB[i], 8);
        accB[i] += __shfl_xor_sync(0xffffffffu, accB[i], 16);
    }

    // remap to per-lane float4 layout via shared staging
    if (myg == 0) {          // lanes 0..7, myh == lane
        float* so = s_out[wslot];
#pragma unroll
        for (int i = 0; i < 8; i++) so[8 * lane + i] = accA[i];
#pragma unroll
        for (int i = 0; i < 8; i++) so[64 + 8 * lane + i] = accB[i];
    }
    __syncwarp();
    float4 res = *(const float4*)&s_out[wslot][4 * lane];

    // cached-region tail (0..3 edges): whole-warp, r via shuffle, 8B/lane load
    for (; jb < cend; jb++) {
        int r = __shfl_sync(0xffffffffu, r_lane, jb - start);
        float ex = __expf(lrelu(pn_my + g_pr[r * NHEAD + myh])) * invd_my;
        ex += __shfl_xor_sync(0xffffffffu, ex, 1);
        ex += __shfl_xor_sync(0xffffffffu, ex, 2);
        ex += __shfl_xor_sync(0xffffffffu, ex, 4);
        float a = ex * 0.125f;
        const uint2* row2 = (const uint2*)(g_xrh4 + r * 16);
        uint2 u = row2[lane];
        float2 qa = __half22float2(*(__half2*)&u.x);
        float2 qb = __half22float2(*(__half2*)&u.y);
        res.x += a * qa.x;
        res.y += a * qa.y;
        res.z += a * qb.x;
        res.w += a * qb.y;
    }

    // overflow region (degree > 32, rare): load r from g_elist
    for (int j = start + 32; j < end; j++) {
        int r = g_elist[j];
        float ex = __expf(lrelu(pn_my + g_pr[r * NHEAD + myh])) * invd_my;
        ex += __shfl_xor_sync(0xffffffffu, ex, 1);
        ex += __shfl_xor_sync(0xffffffffu, ex, 2);
        ex += __shfl_xor_sync(0xffffffffu, ex, 4);
        float a = ex * 0.125f;
        const uint2* row2 = (const uint2*)(g_xrh4 + r * 16);
        uint2 u = row2[lane];
        float2 qa = __half22float2(*(__half2*)&u.x);
        float2 qb = __half22float2(*(__half2*)&u.y);
        res.x += a * qa.x;
        res.y += a * qa.y;
        res.z += a * qb.x;
        res.w += a * qb.y;
    }

    // streaming store: keep hot structures resident in L2
    __stcs((float4*)(out + (long)node * (2 * DIM) + side * DIM) + lane, res);
}

// ---------------- launch ------------------------------------------------------
extern "C" void kernel_launch(void* const* d_in, const int* in_sizes, int n_in,
                              void* d_out, int out_size) {
    const float* x_e = (const float*)d_in[0];
    const float* x_r = (const float*)d_in[1];
    const float* Wh  = (const float*)d_in[2];
    const float* Wt  = (const float*)d_in[3];
    const float* Wr  = (const float*)d_in[4];
    const void*  ei  = d_in[5];
    const void*  rel = d_in[6];
    int E = in_sizes[6];          // element count of rel == number of edges

    k_zero_detect<<<(NSEG + 255) / 256, 256>>>((const unsigned*)ei);
    k_cvt<<<(NR * DIM / 4 + 255) / 256, 256>>>(x_r);

    k_proj<<<(NE * 32 + 255) / 256, 256>>>(x_e, Wh, Wt, NE, 0);
    k_proj<<<(NR * 32 + 255) / 256, 256>>>(x_r, Wr, nullptr, NR, 1);

    k_hist<<<(E + 255) / 256, 256>>>(ei, rel, E);

    k_scan_a<<<NTILES, 256>>>();
    k_scan_b<<<1, 256>>>(E);
    k_scan_c<<<NTILES, 512>>>();

    k_fill<<<(E + 255) / 256, 256>>>(E);

    k_agg<<<(NSEG * 32 + 255) / 256, 256>>>((float*)d_out);
}

// round 10
// speedup vs baseline: 1.0417x; 1.0417x over previous
#include <cuda_runtime.h>
#include <cuda_bf16.h>
#include <cuda_fp16.h>
#include <cstdint>

// Problem constants (fixed by the dataset)
#define NE 50000
#define NR 2000
#define EMAX 800000
#define NHEAD 8
#define DIM 128
#define NEG_SLOPE 0.01f
#define NSEG (2 * NE)
#define TILE 512
#define NTILES ((NSEG + TILE - 1) / TILE)   // 196

// grid partition for the fused prep kernel
#define ZBLK ((NSEG + 255) / 256)           // zero + detect
#define CVTBLK ((NR * DIM / 4 + 255) / 256) // x_r -> fp16
#define PEBLK (NE * 32 / 256)               // proj x_e
#define PRBLK (NR * 32 / 256)               // proj x_r

// ---------------- scratch (static device globals; no allocation) -------------
__device__ float g_ph[NE * NHEAD];      // x_e @ Wh.T
__device__ float g_pt[NE * NHEAD];      // x_e @ Wt.T
__device__ float g_pr[NR * NHEAD];      // x_r @ Wr.T
__device__ uint4 g_xrh4[NR * DIM / 8];  // x_r in fp16, 16 uint4 (256B) per row
__device__ int   g_deg[NSEG];           // degrees: [0,NE)=h side, [NE,2NE)=t side
__device__ int   g_coffs[NSEG + 1];     // exclusive offsets (combined h|t CSR)
__device__ int   g_cur[NSEG];           // scatter cursors
__device__ int   g_elist[2 * EMAX];     // rel id per slot, grouped by (side,node)
__device__ int4  g_htr[EMAX];           // decoded (h, t, r, pad) per edge
__device__ int   g_tsum[NTILES];        // per-tile degree sums
__device__ int   g_is64;                // 1 if edge_index/rel are int64

__device__ __forceinline__ float lrelu(float s) {
    return (s > 0.0f) ? s : NEG_SLOPE * s;
}

// ---------------- warp-per-row projection helper ------------------------------
__device__ __forceinline__ void proj_rows(const float* __restrict__ x,
                                          const float* __restrict__ Wa,
                                          const float* __restrict__ Wb,
                                          float* pa, float* pb, int bid) {
    int w = (bid * 256 + threadIdx.x) >> 5;
    int lane = threadIdx.x & 31;
    const float* xr = x + (long)w * DIM;
    float x0 = xr[lane], x1 = xr[lane + 32], x2 = xr[lane + 64], x3 = xr[lane + 96];
#pragma unroll
    for (int h = 0; h < NHEAD; h++) {
        const float* wa = Wa + h * DIM;
        float a = x0 * wa[lane] + x1 * wa[lane + 32] + x2 * wa[lane + 64] + x3 * wa[lane + 96];
#pragma unroll
        for (int off = 16; off > 0; off >>= 1) a += __shfl_xor_sync(0xffffffffu, a, off);
        if (lane == 0) pa[w * NHEAD + h] = a;
        if (pb) {
            const float* wb = Wb + h * DIM;
            float b = x0 * wb[lane] + x1 * wb[lane + 32] + x2 * wb[lane + 64] + x3 * wb[lane + 96];
#pragma unroll
            for (int off = 16; off > 0; off >>= 1) b += __shfl_xor_sync(0xffffffffu, b, off);
            if (lane == 0) pb[w * NHEAD + h] = b;
        }
    }
}

// ---------------- kernel 1: fused zero + detect + cvt + projections ----------
__global__ __launch_bounds__(256) void k_prep(const unsigned* __restrict__ ei_words,
                                              const float* __restrict__ x_e,
                                              const float* __restrict__ x_r,
                                              const float* __restrict__ Wh,
                                              const float* __restrict__ Wt,
                                              const float* __restrict__ Wr) {
    int bid = blockIdx.x;
    if (bid < ZBLK) {
        int i = bid * 256 + threadIdx.x;
        if (i < NSEG) g_deg[i] = 0;
        if (bid == 0 && threadIdx.x < 32) {
            unsigned w = ei_words[2 * threadIdx.x + 1];
            unsigned ball = __ballot_sync(0xffffffffu, w == 0u);
            if (threadIdx.x == 0) g_is64 = (ball == 0xffffffffu) ? 1 : 0;
        }
        return;
    }
    bid -= ZBLK;
    if (bid < CVTBLK) {
        int i = bid * 256 + threadIdx.x;
        if (i < NR * DIM / 4) {
            float4 v = ((const float4*)x_r)[i];
            __half2* dst = (__half2*)g_xrh4;
            dst[i * 2]     = __floats2half2_rn(v.x, v.y);
            dst[i * 2 + 1] = __floats2half2_rn(v.z, v.w);
        }
        return;
    }
    bid -= CVTBLK;
    if (bid < PEBLK) { proj_rows(x_e, Wh, Wt, g_ph, g_pt, bid); return; }
    bid -= PEBLK;
    proj_rows(x_r, Wr, nullptr, g_pr, nullptr, bid);
}

// ---------------- kernel 2: decode + degree histogram (1 edge/thread) --------
__global__ __launch_bounds__(256) void k_hist(const void* __restrict__ ei,
                                              const void* __restrict__ rel, int E) {
    int e = blockIdx.x * blockDim.x + threadIdx.x;
    if (e >= E) return;
    int is64 = g_is64;
    int h, t, r;
    if (is64) {
        h = (int)((const long long*)ei)[e];
        t = (int)((const long long*)ei)[(long)E + e];
        r = (int)((const long long*)rel)[e];
    } else {
        h = ((const int*)ei)[e];
        t = ((const int*)ei)[(long)E + e];
        r = ((const int*)rel)[e];
    }
    g_htr[e] = make_int4(h, t, r, 0);
    atomicAdd(&g_deg[h], 1);
    atomicAdd(&g_deg[NE + t], 1);
}

// ---------------- kernel 3a: per-tile degree sums -----------------------------
__global__ __launch_bounds__(256) void k_scan_a() {
    __shared__ int sh[256];
    int tid = threadIdx.x;
    int i0 = blockIdx.x * TILE + tid * 2;
    int v = 0;
    if (i0 < NSEG) v += g_deg[i0];
    if (i0 + 1 < NSEG) v += g_deg[i0 + 1];
    sh[tid] = v;
    __syncthreads();
    for (int off = 128; off > 0; off >>= 1) {
        if (tid < off) sh[tid] += sh[tid + off];
        __syncthreads();
    }
    if (tid == 0) g_tsum[blockIdx.x] = sh[0];
}

// ---------------- kernel 3b: tile scan with embedded top-level scan ----------
__global__ __launch_bounds__(512) void k_scan_c(int E) {
    __shared__ int stop[256];
    __shared__ int stile[512];
    int tid = threadIdx.x;
    // redundant top-level inclusive scan of tile sums in every block (cheap)
    if (tid < 256) stop[tid] = (tid < NTILES) ? g_tsum[tid] : 0;
    __syncthreads();
    for (int off = 1; off < 256; off <<= 1) {
        int t = 0;
        if (tid < 256 && tid >= off) t = stop[tid - off];
        __syncthreads();
        if (tid < 256) stop[tid] += t;
        __syncthreads();
    }
    int tile_off = (blockIdx.x == 0) ? 0 : stop[blockIdx.x - 1];
    // local scan of this 512-entry tile
    int idx = blockIdx.x * TILE + tid;
    int v = (idx < NSEG) ? g_deg[idx] : 0;
    stile[tid] = v;
    __syncthreads();
    for (int off = 1; off < 512; off <<= 1) {
        int t = 0;
        if (tid >= off) t = stile[tid - off];
        __syncthreads();
        stile[tid] += t;
        __syncthreads();
    }
    if (idx < NSEG) {
        int excl = tile_off + stile[tid] - v;
        g_coffs[idx] = excl;
        g_cur[idx] = excl;
    }
    if (blockIdx.x == 0 && tid == 0) g_coffs[NSEG] = 2 * E;
}

// ---------------- kernel 4: counting-sort scatter (one int4 load/edge) -------
__global__ __launch_bounds__(256) void k_fill(int E) {
    int e = blockIdx.x * blockDim.x + threadIdx.x;
    if (e >= E) return;
    int4 v = g_htr[e];
    int p1 = atomicAdd(&g_cur[v.x], 1);
    g_elist[p1] = v.z;
    int p2 = atomicAdd(&g_cur[NE + v.y], 1);
    g_elist[p2] = v.z;
}

// ---------------- kernel 5: softmax + aggregation (byte-identical to R8) -----
// One warp per (side, node). Recompute alphas in phase 2; 4 edges/iter via
// 8-lane groups; x_r gathered as fp16 (2x16B per lane), fp32 accumulation.
__global__ __launch_bounds__(256) void k_agg(float* __restrict__ out) {
    __shared__ __align__(16) float s_out[8][128];
    int wslot = threadIdx.x >> 5;
    int gw = (blockIdx.x * blockDim.x + threadIdx.x) >> 5;
    int lane = threadIdx.x & 31;
    if (gw >= NSEG) return;
    int side = (gw >= NE) ? 1 : 0;
    int node = side ? (gw - NE) : gw;
    const float* p = side ? g_pt : g_ph;

    int start = g_coffs[gw];
    int end = g_coffs[gw + 1];

    const float4* pn4 = (const float4*)(p + node * NHEAD);
    float4 pnA = pn4[0], pnB = pn4[1];
    float pn[NHEAD] = {pnA.x, pnA.y, pnA.z, pnA.w, pnB.x, pnB.y, pnB.z, pnB.w};

    // ---- phase 1: denominators per head -------------------------------------
    float exs[NHEAD];
#pragma unroll
    for (int h = 0; h < NHEAD; h++) exs[h] = 0.0f;
    for (int j = start + lane; j < end; j += 32) {
        int r = g_elist[j];
        const float4* pr4 = (const float4*)(g_pr + r * NHEAD);
        float4 A = pr4[0], B = pr4[1];
        exs[0] += __expf(lrelu(pn[0] + A.x));
        exs[1] += __expf(lrelu(pn[1] + A.y));
        exs[2] += __expf(lrelu(pn[2] + A.z));
        exs[3] += __expf(lrelu(pn[3] + A.w));
        exs[4] += __expf(lrelu(pn[4] + B.x));
        exs[5] += __expf(lrelu(pn[5] + B.y));
        exs[6] += __expf(lrelu(pn[6] + B.z));
        exs[7] += __expf(lrelu(pn[7] + B.w));
    }
#pragma unroll
    for (int h = 0; h < NHEAD; h++) {
        float v = exs[h];
#pragma unroll
        for (int off = 16; off > 0; off >>= 1) v += __shfl_xor_sync(0xffffffffu, v, off);
        exs[h] = v;
    }

    int myh = lane & 7;
    int myg = lane >> 3;
    float pn_my = 0.0f, den_my = 0.0f;
#pragma unroll
    for (int h = 0; h < NHEAD; h++) {
        pn_my = (myh == h) ? pn[h] : pn_my;
        den_my = (myh == h) ? exs[h] : den_my;
    }
    float invd_my = 1.0f / (den_my + 1e-16f);

    // ---- phase 2: 4 edges/iter via 8-lane groups; fp16 row gathers ----------
    float accA[8], accB[8];
#pragma unroll
    for (int i = 0; i < 8; i++) { accA[i] = 0.0f; accB[i] = 0.0f; }

#define PROC4(BASE)                                                            \
    {                                                                          \
        int r = g_elist[(BASE) + myg];                                         \
        float ex = __expf(lrelu(pn_my + g_pr[r * NHEAD + myh])) * invd_my;     \
        ex += __shfl_xor_sync(0xffffffffu, ex, 1);                             \
        ex += __shfl_xor_sync(0xffffffffu, ex, 2);                             \
        ex += __shfl_xor_sync(0xffffffffu, ex, 4);                             \
        float a = ex * 0.125f;                                                 \
        const uint4* row = g_xrh4 + r * 16;                                    \
        uint4 u0 = row[myh];                                                   \
        uint4 u1 = row[myh + 8];                                               \
        float2 q;                                                              \
        q = __half22float2(*(__half2*)&u0.x); accA[0] += a * q.x; accA[1] += a * q.y; \
        q = __half22float2(*(__half2*)&u0.y); accA[2] += a * q.x; accA[3] += a * q.y; \
        q = __half22float2(*(__half2*)&u0.z); accA[4] += a * q.x; accA[5] += a * q.y; \
        q = __half22float2(*(__half2*)&u0.w); accA[6] += a * q.x; accA[7] += a * q.y; \
        q = __half22float2(*(__half2*)&u1.x); accB[0] += a * q.x; accB[1] += a * q.y; \
        q = __half22float2(*(__half2*)&u1.y); accB[2] += a * q.x; accB[3] += a * q.y; \
        q = __half22float2(*(__half2*)&u1.z); accB[4] += a * q.x; accB[5] += a * q.y; \
        q = __half22float2(*(__half2*)&u1.w); accB[6] += a * q.x; accB[7] += a * q.y; \
    }

    int jb = start;
    for (; jb + 8 <= end; jb += 8) {
        PROC4(jb)
        PROC4(jb + 4)
    }
    if (jb + 4 <= end) {
        PROC4(jb)
        jb += 4;
    }
#undef PROC4

    // reduce accumulators across the 4 groups (xor 8, 16)
#pragma unroll
    for (int i = 0; i < 8; i++) {
        accA[i] += __shfl_xor_sync(0xffffffffu, accA[i], 8);
        accA[i] += __shfl_xor_sync(0xffffffffu, accA[i], 16);
        accB[i] += __shfl_xor_sync(0xffffffffu, accB[i], 8);
        accB[i] += __shfl_xor_sync(0xffffffffu, accB[i], 16);
    }

    // remap to per-lane float4 layout via shared staging
    if (myg == 0) {          // lanes 0..7, myh == lane
        float* so = s_out[wslot];
#pragma unroll
        for (int i = 0; i < 8; i++) so[8 * lane + i] = accA[i];
#pragma unroll
        for (int i = 0; i < 8; i++) so[64 + 8 * lane + i] = accB[i];
    }
    __syncwarp();
    float4 res = *(const float4*)&s_out[wslot][4 * lane];

    // tail (0..3 edges): whole-warp, each lane loads its own 4 columns (8B)
    for (; jb < end; jb++) {
        int r = g_elist[jb];                      // uniform -> broadcast
        float ex = __expf(lrelu(pn_my + g_pr[r * NHEAD + myh])) * invd_my;
        ex += __shfl_xor_sync(0xffffffffu, ex, 1);
        ex += __shfl_xor_sync(0xffffffffu, ex, 2);
        ex += __shfl_xor_sync(0xffffffffu, ex, 4);
        float a = ex * 0.125f;
        const uint2* row2 = (const uint2*)(g_xrh4 + r * 16);
        uint2 u = row2[lane];
        float2 qa = __half22float2(*(__half2*)&u.x);
        float2 qb = __half22float2(*(__half2*)&u.y);
        res.x += a * qa.x;
        res.y += a * qa.y;
        res.z += a * qb.x;
        res.w += a * qb.y;
    }

    // streaming store: keep hot structures resident in L2
    __stcs((float4*)(out + (long)node * (2 * DIM) + side * DIM) + lane, res);
}

// ---------------- launch ------------------------------------------------------
extern "C" void kernel_launch(void* const* d_in, const int* in_sizes, int n_in,
                              void* d_out, int out_size) {
    const float* x_e = (const float*)d_in[0];
    const float* x_r = (const float*)d_in[1];
    const float* Wh  = (const float*)d_in[2];
    const float* Wt  = (const float*)d_in[3];
    const float* Wr  = (const float*)d_in[4];
    const void*  ei  = d_in[5];
    const void*  rel = d_in[6];
    int E = in_sizes[6];          // element count of rel == number of edges

    k_prep<<<ZBLK + CVTBLK + PEBLK + PRBLK, 256>>>((const unsigned*)ei, x_e, x_r,
                                                   Wh, Wt, Wr);

    k_hist<<<(E + 255) / 256, 256>>>(ei, rel, E);

    k_scan_a<<<NTILES, 256>>>();
    k_scan_c<<<NTILES, 512>>>(E);

    k_fill<<<(E + 255) / 256, 256>>>(E);

    k_agg<<<(NSEG * 32 + 255) / 256, 256>>>((float*)d_out);
}